// round 1
// baseline (speedup 1.0000x reference)
#include <cuda_runtime.h>
#include <math.h>

#define N5 5000
#define EE 256

// ---------------- scratch (device globals; no allocation allowed) ----------------
__device__ float g_win[100000000];        // [4][5000][5000] = 400 MB
__device__ float g_colpart[4*40*5000];    // per-(z, rowblock) partial column sums
__device__ float g_col[4*5000];           // max(sqrt(colsum), eps)
__device__ float g_h[5000*128];           // current activations (normalized)
__device__ float g_base[5000*128];        // x@W0 base / post-elu activations
__device__ float g_P[4*5000*128];         // P_k = h @ W[k+1]
__device__ float g_part[8*5000*128];      // split-K partials for win-apply
__device__ float g_des[5000*256];
__device__ float g_mn[256];
__device__ float g_mx[256];

__device__ __forceinline__ float eluf(float v){ return v > 0.f ? v : expm1f(v); }

// ---------------- column min/max (axis=0) ----------------
__global__ void k_colminmax(const float* __restrict__ xsrc, int C)
{
    const float* src = xsrc ? xsrc : g_base;
    int c = blockIdx.x;
    float mn = 3.4e38f, mx = -3.4e38f;
    for (int n = threadIdx.x; n < N5; n += blockDim.x){
        float v = src[(size_t)n*C + c];
        mn = fminf(mn, v); mx = fmaxf(mx, v);
    }
    __shared__ float smn[256], smx[256];
    smn[threadIdx.x] = mn; smx[threadIdx.x] = mx; __syncthreads();
    for (int s = 128; s > 0; s >>= 1){
        if (threadIdx.x < s){
            smn[threadIdx.x] = fminf(smn[threadIdx.x], smn[threadIdx.x+s]);
            smx[threadIdx.x] = fmaxf(smx[threadIdx.x], smx[threadIdx.x+s]);
        }
        __syncthreads();
    }
    if (threadIdx.x == 0){ g_mn[c] = smn[0]; g_mx[c] = smx[0]; }
}

__global__ void k_apply(const float* __restrict__ xsrc, int C)
{
    const float* src = xsrc ? xsrc : g_base;
    int total = N5*C;
    for (int idx = blockIdx.x*blockDim.x + threadIdx.x; idx < total;
         idx += gridDim.x*blockDim.x){
        int c = idx % C;
        g_h[idx] = (src[idx] - g_mn[c]) / (g_mx[c] - g_mn[c]);
    }
}

// ---------------- build Win: M = ((V*clk_k) @ V^T * a_j)^2, partial col sums ----------------
__global__ __launch_bounds__(256) void k_build(const float* __restrict__ V,
                                               const float* __restrict__ clk,
                                               const float* __restrict__ A)
{
    const int z = blockIdx.z;
    const int kcol = 31 - 8*z;             // SCALE_KS = {31,23,15,7}
    const int bi = blockIdx.y, bj = blockIdx.x;
    const int t = threadIdx.x;
    const int lrow = t >> 1, seg = t & 1;
    const int tx = t & 15, ty = t >> 4;
    const int gRowA = bi*128 + lrow;
    const int gRowB = bj*128 + lrow;

    __shared__ float As[8][128];
    __shared__ float Bs[8][128];
    __shared__ float scol2[16][128];

    float acc[8][8];
#pragma unroll
    for (int r = 0; r < 8; r++)
#pragma unroll
        for (int c = 0; c < 8; c++) acc[r][c] = 0.f;

    for (int k0 = 0; k0 < EE; k0 += 8){
        int e = k0 + seg*4;
        float4 va = make_float4(0,0,0,0), vb = make_float4(0,0,0,0);
        if (gRowA < N5) va = *(const float4*)&V[(size_t)gRowA*EE + e];
        if (gRowB < N5) vb = *(const float4*)&V[(size_t)gRowB*EE + e];
        As[seg*4+0][lrow] = va.x * clk[(e+0)*32 + kcol];
        As[seg*4+1][lrow] = va.y * clk[(e+1)*32 + kcol];
        As[seg*4+2][lrow] = va.z * clk[(e+2)*32 + kcol];
        As[seg*4+3][lrow] = va.w * clk[(e+3)*32 + kcol];
        Bs[seg*4+0][lrow] = vb.x;
        Bs[seg*4+1][lrow] = vb.y;
        Bs[seg*4+2][lrow] = vb.z;
        Bs[seg*4+3][lrow] = vb.w;
        __syncthreads();
#pragma unroll
        for (int kk = 0; kk < 8; kk++){
            float ra[8], rb[8];
#pragma unroll
            for (int r = 0; r < 8; r++) ra[r] = As[kk][ty*8+r];
#pragma unroll
            for (int c = 0; c < 8; c++) rb[c] = Bs[kk][tx*8+c];
#pragma unroll
            for (int r = 0; r < 8; r++)
#pragma unroll
                for (int c = 0; c < 8; c++) acc[r][c] += ra[r]*rb[c];
        }
        __syncthreads();
    }

    float aj[8];
#pragma unroll
    for (int c = 0; c < 8; c++){
        int j = bj*128 + tx*8 + c;
        aj[c] = (j < N5) ? A[j] : 0.f;
    }
#pragma unroll
    for (int c = 0; c < 8; c++){
        int j = bj*128 + tx*8 + c;
        float s = 0.f;
        if (j < N5){
#pragma unroll
            for (int r = 0; r < 8; r++){
                int i = bi*128 + ty*8 + r;
                if (i < N5){
                    float m = acc[r][c]*aj[c];
                    m = m*m;
                    g_win[(size_t)z*N5*N5 + (size_t)i*N5 + j] = m;
                    s += m*m;
                }
            }
        }
        scol2[ty][tx*8+c] = s;
    }
    __syncthreads();
    if (t < 128){
        float s = 0.f;
#pragma unroll
        for (int r = 0; r < 16; r++) s += scol2[r][t];
        int j = bj*128 + t;
        if (j < N5) g_colpart[((size_t)z*40 + bi)*N5 + j] = s;
    }
}

__global__ void k_colreduce()
{
    int z = blockIdx.y;
    int j = blockIdx.x*blockDim.x + threadIdx.x;
    if (j < N5){
        float s = 0.f;
        for (int b = 0; b < 40; b++) s += g_colpart[((size_t)z*40 + b)*N5 + j];
        g_col[z*N5 + j] = fmaxf(sqrtf(s), 1e-12f);
    }
}

__global__ void k_winnorm()
{
    int z = blockIdx.z;
    int i = blockIdx.y;
    int j = blockIdx.x*blockDim.x + threadIdx.x;
    if (j < N5){
        size_t idx = (size_t)z*N5*N5 + (size_t)i*N5 + j;
        float v = g_win[idx] / g_col[z*N5 + j];
        g_win[idx] = v*v;
    }
}

// ---------------- small projection: base = h@W[0], P_k = h@W[k+1]; or des ----------------
template<int CI, int CO, int MODE>   // MODE 0: base/P per blockIdx.y; MODE 1: des (bias+elu)
__global__ __launch_bounds__(256) void k_proj(const float* __restrict__ W,
                                              const float* __restrict__ bias)
{
    constexpr int PER = (64*CO)/256;
    const int j = blockIdx.y;
    const float* Wj = W + (size_t)j*CI*CO;
    const int r0 = blockIdx.x*64;
    const int t = threadIdx.x;

    __shared__ float ht[64][33];
    __shared__ float Wt[32][CO+1];

    float acc[PER];
#pragma unroll
    for (int p = 0; p < PER; p++) acc[p] = 0.f;

    for (int c0 = 0; c0 < CI; c0 += 32){
        for (int idx = t; idx < 64*32; idx += 256){
            int r = idx >> 5, cc = idx & 31;
            int gr = r0 + r;
            ht[r][cc] = (gr < N5) ? g_h[(size_t)gr*CI + c0 + cc] : 0.f;
        }
        for (int idx = t; idx < 32*CO; idx += 256){
            int cc = idx / CO, o = idx % CO;
            Wt[cc][o] = Wj[(size_t)(c0+cc)*CO + o];
        }
        __syncthreads();
#pragma unroll
        for (int p = 0; p < PER; p++){
            int oi = t + p*256;
            int r = oi / CO, o = oi % CO;
            float s = acc[p];
#pragma unroll
            for (int cc = 0; cc < 32; cc++) s += ht[r][cc]*Wt[cc][o];
            acc[p] = s;
        }
        __syncthreads();
    }
    float* out;
    if (MODE == 1) out = g_des;
    else out = (j == 0) ? g_base : g_P + (size_t)(j-1)*N5*CO;
#pragma unroll
    for (int p = 0; p < PER; p++){
        int oi = t + p*256;
        int r = oi / CO, o = oi % CO;
        int gr = r0 + r;
        if (gr < N5){
            float v = acc[p];
            if (MODE == 1) v = eluf(v + bias[o]);
            out[(size_t)gr*CO + o] = v;
        }
    }
}

// ---------------- big fused GEMM: part_y = Win_slab_chunk @ P_slab ----------------
template<int BN>
__global__ __launch_bounds__(256) void k_winapply()
{
    constexpr int TN = BN/16;
    const int bi = blockIdx.x;
    const int y = blockIdx.y;              // 0..7 split-K chunks
    const int slab = y >> 1;
    const int mstart = (y & 1) ? 2496 : 0;
    const int mend   = (y & 1) ? 5000 : 2496;
    const int r0 = bi*128;
    const int t = threadIdx.x;
    const int lrow = t >> 1, seg = t & 1;
    const int tx = t & 15, ty = t >> 4;

    __shared__ float As[8][128];
    __shared__ float Bs[8][BN];

    float acc[8][TN];
#pragma unroll
    for (int r = 0; r < 8; r++)
#pragma unroll
        for (int c = 0; c < TN; c++) acc[r][c] = 0.f;

    const float* Wk = g_win + (size_t)slab*N5*N5;
    const float* Pk = g_P + (size_t)slab*N5*BN;
    const int gr = r0 + lrow;
    const bool rowok = gr < N5;
    const float* aRow = Wk + (size_t)gr*N5;

    for (int m0 = mstart; m0 < mend; m0 += 8){
        float4 va = make_float4(0,0,0,0);
        if (rowok) va = *(const float4*)&aRow[m0 + seg*4];
        As[seg*4+0][lrow] = va.x; As[seg*4+1][lrow] = va.y;
        As[seg*4+2][lrow] = va.z; As[seg*4+3][lrow] = va.w;
        for (int idx = t; idx < 2*BN; idx += 256){
            int mm = idx / (BN/4);
            int o4 = (idx % (BN/4))*4;
            *(float4*)&Bs[mm][o4] = *(const float4*)&Pk[(size_t)(m0+mm)*BN + o4];
        }
        __syncthreads();
#pragma unroll
        for (int kk = 0; kk < 8; kk++){
            float ra[8], rb[TN];
#pragma unroll
            for (int r = 0; r < 8; r++) ra[r] = As[kk][ty*8+r];
#pragma unroll
            for (int c = 0; c < TN; c++) rb[c] = Bs[kk][tx*TN+c];
#pragma unroll
            for (int r = 0; r < 8; r++)
#pragma unroll
                for (int c = 0; c < TN; c++) acc[r][c] += ra[r]*rb[c];
        }
        __syncthreads();
    }
    float* dst = g_part + (size_t)y*N5*BN;
#pragma unroll
    for (int r = 0; r < 8; r++){
        int i = r0 + ty*8 + r;
        if (i < N5){
#pragma unroll
            for (int c = 0; c < TN; c++)
                dst[(size_t)i*BN + tx*TN + c] = acc[r][c];
        }
    }
}

template<int BN>
__global__ void k_winreduce()
{
    int total = N5*BN;
    for (int idx = blockIdx.x*blockDim.x + threadIdx.x; idx < total;
         idx += gridDim.x*blockDim.x){
        float v = g_base[idx];
#pragma unroll
        for (int s = 0; s < 8; s++) v += g_part[(size_t)s*N5*BN + idx];
        g_base[idx] = eluf(v);
    }
}

// ---------------- logits = des @ fc2_w + fc2_b ----------------
__global__ __launch_bounds__(256) void k_linear_out(const float* __restrict__ B,
                                                    const float* __restrict__ bias,
                                                    float* __restrict__ out)
{
    const int bi = blockIdx.y, bj = blockIdx.x;
    const int t = threadIdx.x;
    const int lrow = t >> 1, seg = t & 1;
    const int tx = t & 15, ty = t >> 4;
    const int gRowA = bi*128 + lrow;

    __shared__ float As[8][128];
    __shared__ float Bs[8][128];

    float acc[8][8];
#pragma unroll
    for (int r = 0; r < 8; r++)
#pragma unroll
        for (int c = 0; c < 8; c++) acc[r][c] = 0.f;

    for (int k0 = 0; k0 < 256; k0 += 8){
        float4 va = make_float4(0,0,0,0);
        if (gRowA < N5) va = *(const float4*)&g_des[(size_t)gRowA*256 + k0 + seg*4];
        As[seg*4+0][lrow] = va.x; As[seg*4+1][lrow] = va.y;
        As[seg*4+2][lrow] = va.z; As[seg*4+3][lrow] = va.w;

        int kk = t >> 5, c4 = (t & 31)*4;
        int gc = bj*128 + c4;
        float4 vb = make_float4(0,0,0,0);
        if (gc + 3 < N5){
            vb = *(const float4*)&B[(size_t)(k0+kk)*N5 + gc];
        } else {
            if (gc+0 < N5) vb.x = B[(size_t)(k0+kk)*N5 + gc+0];
            if (gc+1 < N5) vb.y = B[(size_t)(k0+kk)*N5 + gc+1];
            if (gc+2 < N5) vb.z = B[(size_t)(k0+kk)*N5 + gc+2];
            if (gc+3 < N5) vb.w = B[(size_t)(k0+kk)*N5 + gc+3];
        }
        Bs[kk][c4+0] = vb.x; Bs[kk][c4+1] = vb.y;
        Bs[kk][c4+2] = vb.z; Bs[kk][c4+3] = vb.w;
        __syncthreads();
#pragma unroll
        for (int kk2 = 0; kk2 < 8; kk2++){
            float ra[8], rb[8];
#pragma unroll
            for (int r = 0; r < 8; r++) ra[r] = As[kk2][ty*8+r];
#pragma unroll
            for (int c = 0; c < 8; c++) rb[c] = Bs[kk2][tx*8+c];
#pragma unroll
            for (int r = 0; r < 8; r++)
#pragma unroll
                for (int c = 0; c < 8; c++) acc[r][c] += ra[r]*rb[c];
        }
        __syncthreads();
    }
#pragma unroll
    for (int r = 0; r < 8; r++){
        int i = bi*128 + ty*8 + r;
        if (i < N5){
#pragma unroll
            for (int c = 0; c < 8; c++){
                int j = bj*128 + tx*8 + c;
                if (j < N5) out[(size_t)i*N5 + j] = acc[r][c] + bias[j];
            }
        }
    }
}

__global__ void k_logsoftmax(float* __restrict__ out)
{
    int row = blockIdx.x;
    float* p = out + (size_t)row*N5;
    __shared__ float sh[256];
    float mx = -3.4e38f;
    for (int j = threadIdx.x; j < N5; j += 256) mx = fmaxf(mx, p[j]);
    sh[threadIdx.x] = mx; __syncthreads();
    for (int s = 128; s > 0; s >>= 1){
        if (threadIdx.x < s) sh[threadIdx.x] = fmaxf(sh[threadIdx.x], sh[threadIdx.x+s]);
        __syncthreads();
    }
    mx = sh[0]; __syncthreads();
    float sum = 0.f;
    for (int j = threadIdx.x; j < N5; j += 256) sum += expf(p[j]-mx);
    sh[threadIdx.x] = sum; __syncthreads();
    for (int s = 128; s > 0; s >>= 1){
        if (threadIdx.x < s) sh[threadIdx.x] += sh[threadIdx.x+s];
        __syncthreads();
    }
    float lse = mx + logf(sh[0]);
    for (int j = threadIdx.x; j < N5; j += 256) p[j] -= lse;
}

__global__ void k_copydes(float* __restrict__ out)
{
    int total = N5*256;
    for (int idx = blockIdx.x*blockDim.x + threadIdx.x; idx < total;
         idx += gridDim.x*blockDim.x)
        out[idx] = g_des[idx];
}

// ---------------- launcher ----------------
extern "C" void kernel_launch(void* const* d_in, const int* in_sizes, int n_in,
                              void* d_out, int out_size)
{
    (void)in_sizes; (void)n_in;
    const float* x    = (const float*)d_in[0];
    const float* V    = (const float*)d_in[1];
    const float* A    = (const float*)d_in[2];
    const float* clk  = (const float*)d_in[3];
    const float* Wc[6] = {(const float*)d_in[4], (const float*)d_in[5],
                          (const float*)d_in[6], (const float*)d_in[7],
                          (const float*)d_in[8], (const float*)d_in[9]};
    const float* fc1w = (const float*)d_in[10];
    const float* fc1b = (const float*)d_in[11];
    const float* fc2w = (const float*)d_in[12];
    const float* fc2b = (const float*)d_in[13];
    float* out = (float*)d_out;

    // Build Win
    k_build<<<dim3(40,40,4),256>>>(V, clk, A);
    k_colreduce<<<dim3(20,4),256>>>();
    k_winnorm<<<dim3(5,5000,4),1024>>>();

    // h = fmaxmin(x)
    k_colminmax<<<128,256>>>(x, 128);
    k_apply<<<640,256>>>(x, 128);

    // Layer 1: 128 -> 96
    k_proj<128,96,0><<<dim3(79,5),256>>>(Wc[0], nullptr);
    k_winapply<96><<<dim3(40,8),256>>>();
    k_winreduce<96><<<480,256>>>();
    k_colminmax<<<96,256>>>(nullptr, 96);
    k_apply<<<480,256>>>(nullptr, 96);

    // Layers 2-5: 96 -> 96
    for (int L = 1; L < 5; L++){
        k_proj<96,96,0><<<dim3(79,5),256>>>(Wc[L], nullptr);
        k_winapply<96><<<dim3(40,8),256>>>();
        k_winreduce<96><<<480,256>>>();
        k_colminmax<<<96,256>>>(nullptr, 96);
        k_apply<<<480,256>>>(nullptr, 96);
    }

    // Layer 6: 96 -> 128
    k_proj<96,128,0><<<dim3(79,5),256>>>(Wc[5], nullptr);
    k_winapply<128><<<dim3(40,8),256>>>();
    k_winreduce<128><<<640,256>>>();
    k_colminmax<<<128,256>>>(nullptr, 128);
    k_apply<<<640,256>>>(nullptr, 128);

    // des = elu(h @ fc1_w + fc1_b)
    k_proj<128,256,1><<<dim3(79,1),256>>>(fc1w, fc1b);

    // logits + log_softmax
    k_linear_out<<<dim3(40,40),256>>>(fc2w, fc2b, out);
    k_logsoftmax<<<5000,256>>>(out);

    // second output: des
    if (out_size >= 25000000 + N5*256)
        k_copydes<<<640,256>>>(out + 25000000);
}

// round 2
// speedup vs baseline: 2.3905x; 2.3905x over previous
#include <cuda_runtime.h>
#include <math.h>

#define N5 5000

// ---------------- scratch (device globals; no allocation allowed) ----------------
__device__ float g_win[100000032];        // [4][5000][5000] (+pad for k-overread) = M^2, unnormalized
__device__ float g_colpart[4*40*5000];    // per-(z, rowblock) partial column sums of M^2... (M^2 summed)
__device__ float g_icol2[4*5000];         // 1 / max(sqrt(sum),eps)^2
__device__ float g_h[5000*128];           // current activations (normalized)
__device__ float g_base[5000*128];        // x@W0 base / post-elu activations
__device__ float g_P[4*5000*128];         // P_k = (h @ W[k+1]) * icol2 (row-scaled)
__device__ float g_part[8*5000*128];      // split-K partials for win-apply
__device__ float g_des[5000*256];
__device__ float g_mn[256];
__device__ float g_mx[256];

__device__ __forceinline__ float eluf(float v){ return v > 0.f ? v : expm1f(v); }

__device__ __forceinline__ unsigned tf32r(float f){
    unsigned u; asm("cvt.rna.tf32.f32 %0, %1;" : "=r"(u) : "f"(f)); return u;
}
__device__ __forceinline__ void splitf(float v, unsigned& hi, unsigned& lo){
    unsigned h = tf32r(v);
    lo = tf32r(v - __uint_as_float(h));
    hi = h;
}
__device__ __forceinline__ void mma8(float* c, const unsigned* a, unsigned b0, unsigned b1){
    asm volatile("mma.sync.aligned.m16n8k8.row.col.f32.tf32.tf32.f32 "
        "{%0,%1,%2,%3},{%4,%5,%6,%7},{%8,%9},{%0,%1,%2,%3};"
        : "+f"(c[0]),"+f"(c[1]),"+f"(c[2]),"+f"(c[3])
        : "r"(a[0]),"r"(a[1]),"r"(a[2]),"r"(a[3]),"r"(b0),"r"(b1));
}

// ---------------- column min/max (axis=0) ----------------
__global__ void k_colminmax(const float* __restrict__ xsrc, int C)
{
    const float* src = xsrc ? xsrc : g_base;
    int c = blockIdx.x;
    float mn = 3.4e38f, mx = -3.4e38f;
    for (int n = threadIdx.x; n < N5; n += blockDim.x){
        float v = src[(size_t)n*C + c];
        mn = fminf(mn, v); mx = fmaxf(mx, v);
    }
    __shared__ float smn[256], smx[256];
    smn[threadIdx.x] = mn; smx[threadIdx.x] = mx; __syncthreads();
    for (int s = 128; s > 0; s >>= 1){
        if (threadIdx.x < s){
            smn[threadIdx.x] = fminf(smn[threadIdx.x], smn[threadIdx.x+s]);
            smx[threadIdx.x] = fmaxf(smx[threadIdx.x], smx[threadIdx.x+s]);
        }
        __syncthreads();
    }
    if (threadIdx.x == 0){ g_mn[c] = smn[0]; g_mx[c] = smx[0]; }
}

__global__ void k_apply(const float* __restrict__ xsrc, int C)
{
    const float* src = xsrc ? xsrc : g_base;
    int total = N5*C;
    for (int idx = blockIdx.x*blockDim.x + threadIdx.x; idx < total;
         idx += gridDim.x*blockDim.x){
        int c = idx % C;
        g_h[idx] = (src[idx] - g_mn[c]) / (g_mx[c] - g_mn[c]);
    }
}

// ---------------- build Win (tensor core, split-tf32 for fp32-class accuracy) ----------------
// Stores M^2 (M = ((V*clk_k)@V^T * a_j)^2) and per-block partial column sums of M^2.
__global__ __launch_bounds__(256,2) void k_build_tc(const float* __restrict__ V,
                                                    const float* __restrict__ clk,
                                                    const float* __restrict__ A)
{
    __shared__ unsigned Ah[16][136], Al[16][136], Bh[16][136], Bl[16][136];
    __shared__ float scol[4][128];

    const int z = blockIdx.z;
    const int kcol = 31 - 8*z;
    const int bi = blockIdx.y, bj = blockIdx.x;
    const int t = threadIdx.x;
    const int w = t >> 5, lane = t & 31, g = lane >> 2, ctg = lane & 3;
    const int wm = w >> 1, wn = w & 1;
    const int r = t >> 1, seg = t & 1;
    const int garow = min(bi*128 + r, N5-1);
    const int gbrow = min(bj*128 + r, N5-1);

    float acc[2][8][4];
#pragma unroll
    for (int mt = 0; mt < 2; mt++)
#pragma unroll
        for (int nt = 0; nt < 8; nt++)
#pragma unroll
            for (int q = 0; q < 4; q++) acc[mt][nt][q] = 0.f;

    for (int c = 0; c < 16; c++){
        const int k0 = c*16;
        __syncthreads();
#pragma unroll
        for (int j = 0; j < 2; j++){
            int col = seg*8 + j*4;
            float4 va = *(const float4*)&V[(size_t)garow*256 + k0 + col];
            va.x *= clk[(k0+col+0)*32 + kcol];
            va.y *= clk[(k0+col+1)*32 + kcol];
            va.z *= clk[(k0+col+2)*32 + kcol];
            va.w *= clk[(k0+col+3)*32 + kcol];
            unsigned h0,l0,h1,l1,h2,l2,h3,l3;
            splitf(va.x,h0,l0); splitf(va.y,h1,l1); splitf(va.z,h2,l2); splitf(va.w,h3,l3);
            Ah[col+0][r]=h0; Al[col+0][r]=l0;
            Ah[col+1][r]=h1; Al[col+1][r]=l1;
            Ah[col+2][r]=h2; Al[col+2][r]=l2;
            Ah[col+3][r]=h3; Al[col+3][r]=l3;

            float4 vb = *(const float4*)&V[(size_t)gbrow*256 + k0 + col];
            splitf(vb.x,h0,l0); splitf(vb.y,h1,l1); splitf(vb.z,h2,l2); splitf(vb.w,h3,l3);
            Bh[col+0][r]=h0; Bl[col+0][r]=l0;
            Bh[col+1][r]=h1; Bl[col+1][r]=l1;
            Bh[col+2][r]=h2; Bl[col+2][r]=l2;
            Bh[col+3][r]=h3; Bl[col+3][r]=l3;
        }
        __syncthreads();
#pragma unroll
        for (int kk = 0; kk < 2; kk++){
            const int k = kk*8;
            unsigned ah[2][4], al[2][4];
#pragma unroll
            for (int mt = 0; mt < 2; mt++){
                int m0 = wm*32 + mt*16;
                ah[mt][0]=Ah[k+ctg][m0+g];   ah[mt][1]=Ah[k+ctg][m0+g+8];
                ah[mt][2]=Ah[k+ctg+4][m0+g]; ah[mt][3]=Ah[k+ctg+4][m0+g+8];
                al[mt][0]=Al[k+ctg][m0+g];   al[mt][1]=Al[k+ctg][m0+g+8];
                al[mt][2]=Al[k+ctg+4][m0+g]; al[mt][3]=Al[k+ctg+4][m0+g+8];
            }
#pragma unroll
            for (int nt = 0; nt < 8; nt++){
                int n = wn*64 + nt*8 + g;
                unsigned bh0 = Bh[k+ctg][n], bh1 = Bh[k+ctg+4][n];
                unsigned bl0 = Bl[k+ctg][n], bl1 = Bl[k+ctg+4][n];
#pragma unroll
                for (int mt = 0; mt < 2; mt++){
                    mma8(acc[mt][nt], ah[mt], bh0, bh1);
                    mma8(acc[mt][nt], ah[mt], bl0, bl1);
                    mma8(acc[mt][nt], al[mt], bh0, bh1);
                }
            }
        }
    }

    // epilogue: m = t*aj; store X = (m*m)^2; column partial sums of X
    const size_t wbase = (size_t)z*25000000;
#pragma unroll
    for (int nt = 0; nt < 8; nt++){
        int jb = bj*128 + wn*64 + nt*8 + ctg*2;
        float aj0 = (jb   < N5) ? A[jb]   : 0.f;
        float aj1 = (jb+1 < N5) ? A[jb+1] : 0.f;
        float se = 0.f, so = 0.f;
#pragma unroll
        for (int mt = 0; mt < 2; mt++){
            int i0 = bi*128 + wm*32 + mt*16 + g;
            float m00 = acc[mt][nt][0]*aj0; float X00 = m00*m00; X00 *= X00;
            float m01 = acc[mt][nt][1]*aj1; float X01 = m01*m01; X01 *= X01;
            float m10 = acc[mt][nt][2]*aj0; float X10 = m10*m10; X10 *= X10;
            float m11 = acc[mt][nt][3]*aj1; float X11 = m11*m11; X11 *= X11;
            bool ok0 = i0 < N5, ok1 = (i0+8) < N5;
            if (ok0 && jb < N5){
                if (jb+1 < N5) *(float2*)&g_win[wbase + (size_t)i0*N5 + jb] = make_float2(X00,X01);
                else g_win[wbase + (size_t)i0*N5 + jb] = X00;
            }
            if (ok1 && jb < N5){
                if (jb+1 < N5) *(float2*)&g_win[wbase + (size_t)(i0+8)*N5 + jb] = make_float2(X10,X11);
                else g_win[wbase + (size_t)(i0+8)*N5 + jb] = X10;
            }
            se += (ok0?X00:0.f) + (ok1?X10:0.f);
            so += (ok0?X01:0.f) + (ok1?X11:0.f);
        }
#pragma unroll
        for (int off = 4; off < 32; off <<= 1){
            se += __shfl_xor_sync(0xffffffffu, se, off);
            so += __shfl_xor_sync(0xffffffffu, so, off);
        }
        if (lane < 4){
            scol[wm][wn*64 + nt*8 + lane*2]     = se;
            scol[wm][wn*64 + nt*8 + lane*2 + 1] = so;
        }
    }
    __syncthreads();
    if (t < 128){
        float s = scol[0][t] + scol[1][t] + scol[2][t] + scol[3][t];
        int j = bj*128 + t;
        if (j < N5) g_colpart[((size_t)z*40 + bi)*N5 + j] = s;
    }
}

__global__ void k_colreduce()
{
    int z = blockIdx.y;
    int j = blockIdx.x*blockDim.x + threadIdx.x;
    if (j < N5){
        float s = 0.f;
        for (int b = 0; b < 40; b++) s += g_colpart[((size_t)z*40 + b)*N5 + j];
        float c = fmaxf(sqrtf(s), 1e-12f);
        g_icol2[z*N5 + j] = 1.0f/(c*c);
    }
}

// ---------------- small projection: base = h@W[0], P_k = (h@W[k+1])*icol2; or des ----------------
template<int CI, int CO, int MODE>   // MODE 0: base/P per blockIdx.y; MODE 1: des (bias+elu)
__global__ __launch_bounds__(256) void k_proj(const float* __restrict__ W,
                                              const float* __restrict__ bias)
{
    constexpr int PER = (64*CO)/256;
    const int j = blockIdx.y;
    const float* Wj = W + (size_t)j*CI*CO;
    const int r0 = blockIdx.x*64;
    const int t = threadIdx.x;

    __shared__ float ht[64][33];
    __shared__ float Wt[32][CO+1];

    float acc[PER];
#pragma unroll
    for (int p = 0; p < PER; p++) acc[p] = 0.f;

    for (int c0 = 0; c0 < CI; c0 += 32){
        for (int idx = t; idx < 64*32; idx += 256){
            int r = idx >> 5, cc = idx & 31;
            int gr = r0 + r;
            ht[r][cc] = (gr < N5) ? g_h[(size_t)gr*CI + c0 + cc] : 0.f;
        }
        for (int idx = t; idx < 32*CO; idx += 256){
            int cc = idx / CO, o = idx % CO;
            Wt[cc][o] = Wj[(size_t)(c0+cc)*CO + o];
        }
        __syncthreads();
#pragma unroll
        for (int p = 0; p < PER; p++){
            int oi = t + p*256;
            int rr = oi / CO, o = oi % CO;
            float s = acc[p];
#pragma unroll
            for (int cc = 0; cc < 32; cc++) s += ht[rr][cc]*Wt[cc][o];
            acc[p] = s;
        }
        __syncthreads();
    }
    float* out;
    if (MODE == 1) out = g_des;
    else out = (j == 0) ? g_base : g_P + (size_t)(j-1)*N5*CO;
#pragma unroll
    for (int p = 0; p < PER; p++){
        int oi = t + p*256;
        int rr = oi / CO, o = oi % CO;
        int gr = r0 + rr;
        if (gr < N5){
            float v = acc[p];
            if (MODE == 1) v = eluf(v + bias[o]);
            else if (j > 0) v *= g_icol2[(j-1)*N5 + gr];
            out[(size_t)gr*CO + o] = v;
        }
    }
}

// ---------------- big fused GEMM (tensor core): part_y = Win_chunk @ Pscaled ----------------
template<int BN>
__global__ __launch_bounds__(256,2) void k_winapply_tc()
{
    constexpr int BP = (BN==96) ? 104 : 136;
    constexpr int NT = BN/16;
    constexpr int NB4 = BN/4;
    constexpr int BCNT = (32*NB4)/256;
    __shared__ unsigned As[32][136];
    __shared__ __align__(16) unsigned Bs[32][BP];

    const int t = threadIdx.x;
    const int w = t >> 5, lane = t & 31, g = lane >> 2, ctg = lane & 3;
    const int wm = w >> 1, wn = w & 1;
    const int bi = blockIdx.x, y = blockIdx.y;
    const int slab = y >> 1;
    const int kbase = (y & 1) ? 2496 : 0;
    const int nch   = (y & 1) ? 79 : 78;
    const float* __restrict__ Wk = g_win + (size_t)slab*25000000;
    const float* __restrict__ Pk = g_P + (size_t)slab*N5*BN;
    const int ar = t >> 1, aseg = t & 1;
    const float* aptr = Wk + (size_t)min(bi*128 + ar, N5-1)*N5;

    float4 aR[4], bR[BCNT];

    {
        const int k0 = kbase + aseg*16;
#pragma unroll
        for (int j = 0; j < 4; j++) aR[j] = *(const float4*)&aptr[k0 + j*4];
#pragma unroll
        for (int i = 0; i < BCNT; i++){
            int idx = t + i*256;
            int br = idx/NB4, bc = idx%NB4;
            int gk = kbase + br;
            bR[i] = (gk < N5) ? *(const float4*)&Pk[(size_t)gk*BN + bc*4]
                              : make_float4(0,0,0,0);
        }
    }

    float acc[2][NT][4];
#pragma unroll
    for (int mt = 0; mt < 2; mt++)
#pragma unroll
        for (int nt = 0; nt < NT; nt++)
#pragma unroll
            for (int q = 0; q < 4; q++) acc[mt][nt][q] = 0.f;

    for (int c = 0; c < nch; c++){
        __syncthreads();
#pragma unroll
        for (int j = 0; j < 4; j++){
            int col = aseg*16 + j*4;
            As[col+0][ar] = tf32r(aR[j].x);
            As[col+1][ar] = tf32r(aR[j].y);
            As[col+2][ar] = tf32r(aR[j].z);
            As[col+3][ar] = tf32r(aR[j].w);
        }
#pragma unroll
        for (int i = 0; i < BCNT; i++){
            int idx = t + i*256;
            int br = idx/NB4, bc = idx%NB4;
            *(uint4*)&Bs[br][bc*4] = make_uint4(tf32r(bR[i].x), tf32r(bR[i].y),
                                                tf32r(bR[i].z), tf32r(bR[i].w));
        }
        __syncthreads();
        if (c+1 < nch){
            const int k0 = kbase + (c+1)*32;
#pragma unroll
            for (int j = 0; j < 4; j++) aR[j] = *(const float4*)&aptr[k0 + aseg*16 + j*4];
#pragma unroll
            for (int i = 0; i < BCNT; i++){
                int idx = t + i*256;
                int br = idx/NB4, bc = idx%NB4;
                int gk = k0 + br;
                bR[i] = (gk < N5) ? *(const float4*)&Pk[(size_t)gk*BN + bc*4]
                                  : make_float4(0,0,0,0);
            }
        }
#pragma unroll
        for (int kk = 0; kk < 4; kk++){
            const int k = kk*8;
            unsigned a[2][4];
#pragma unroll
            for (int mt = 0; mt < 2; mt++){
                int m0 = wm*32 + mt*16;
                a[mt][0]=As[k+ctg][m0+g];   a[mt][1]=As[k+ctg][m0+g+8];
                a[mt][2]=As[k+ctg+4][m0+g]; a[mt][3]=As[k+ctg+4][m0+g+8];
            }
#pragma unroll
            for (int nt = 0; nt < NT; nt++){
                int n = wn*(BN/2) + nt*8 + g;
                unsigned b0 = Bs[k+ctg][n], b1 = Bs[k+ctg+4][n];
                mma8(acc[0][nt], a[0], b0, b1);
                mma8(acc[1][nt], a[1], b0, b1);
            }
        }
    }

    float* dst = g_part + (size_t)y*N5*BN;
#pragma unroll
    for (int mt = 0; mt < 2; mt++){
#pragma unroll
        for (int nt = 0; nt < NT; nt++){
            int i0 = bi*128 + wm*32 + mt*16 + g;
            int n  = wn*(BN/2) + nt*8 + ctg*2;
            if (i0 < N5)
                *(float2*)&dst[(size_t)i0*BN + n] =
                    make_float2(acc[mt][nt][0], acc[mt][nt][1]);
            if (i0+8 < N5)
                *(float2*)&dst[(size_t)(i0+8)*BN + n] =
                    make_float2(acc[mt][nt][2], acc[mt][nt][3]);
        }
    }
}

template<int BN>
__global__ void k_winreduce()
{
    int total = N5*BN;
    for (int idx = blockIdx.x*blockDim.x + threadIdx.x; idx < total;
         idx += gridDim.x*blockDim.x){
        float v = g_base[idx];
#pragma unroll
        for (int s = 0; s < 8; s++) v += g_part[(size_t)s*N5*BN + idx];
        g_base[idx] = eluf(v);
    }
}

// ---------------- logits = des @ fc2_w + fc2_b (tensor core, plain tf32) ----------------
__global__ __launch_bounds__(256,2) void k_linear_tc(const float* __restrict__ B,
                                                     const float* __restrict__ bias,
                                                     float* __restrict__ out)
{
    __shared__ unsigned As[32][136];
    __shared__ __align__(16) unsigned Bs[32][136];

    const int t = threadIdx.x;
    const int w = t >> 5, lane = t & 31, g = lane >> 2, ctg = lane & 3;
    const int wm = w >> 1, wn = w & 1;
    const int bi = blockIdx.y, bj = blockIdx.x;
    const int ar = t >> 1, aseg = t & 1;
    const float* aptr = g_des + (size_t)min(bi*128 + ar, N5-1)*256;

    float acc[2][8][4];
#pragma unroll
    for (int mt = 0; mt < 2; mt++)
#pragma unroll
        for (int nt = 0; nt < 8; nt++)
#pragma unroll
            for (int q = 0; q < 4; q++) acc[mt][nt][q] = 0.f;

    for (int c = 0; c < 8; c++){
        const int k0 = c*32;
        __syncthreads();
#pragma unroll
        for (int j = 0; j < 4; j++){
            int col = aseg*16 + j*4;
            float4 v = *(const float4*)&aptr[k0 + col];
            As[col+0][ar] = tf32r(v.x);
            As[col+1][ar] = tf32r(v.y);
            As[col+2][ar] = tf32r(v.z);
            As[col+3][ar] = tf32r(v.w);
        }
#pragma unroll
        for (int i = 0; i < 4; i++){
            int idx = t + i*256;
            int br = idx >> 5, bc = idx & 31;
            int gj = bj*128 + bc*4;
            float4 v;
            if (gj + 3 < N5) v = *(const float4*)&B[(size_t)(k0+br)*N5 + gj];
            else {
                v = make_float4(0,0,0,0);
                if (gj+0 < N5) v.x = B[(size_t)(k0+br)*N5 + gj+0];
                if (gj+1 < N5) v.y = B[(size_t)(k0+br)*N5 + gj+1];
                if (gj+2 < N5) v.z = B[(size_t)(k0+br)*N5 + gj+2];
                if (gj+3 < N5) v.w = B[(size_t)(k0+br)*N5 + gj+3];
            }
            *(uint4*)&Bs[br][bc*4] = make_uint4(tf32r(v.x), tf32r(v.y), tf32r(v.z), tf32r(v.w));
        }
        __syncthreads();
#pragma unroll
        for (int kk = 0; kk < 4; kk++){
            const int k = kk*8;
            unsigned a[2][4];
#pragma unroll
            for (int mt = 0; mt < 2; mt++){
                int m0 = wm*32 + mt*16;
                a[mt][0]=As[k+ctg][m0+g];   a[mt][1]=As[k+ctg][m0+g+8];
                a[mt][2]=As[k+ctg+4][m0+g]; a[mt][3]=As[k+ctg+4][m0+g+8];
            }
#pragma unroll
            for (int nt = 0; nt < 8; nt++){
                int n = wn*64 + nt*8 + g;
                unsigned b0 = Bs[k+ctg][n], b1 = Bs[k+ctg+4][n];
                mma8(acc[0][nt], a[0], b0, b1);
                mma8(acc[1][nt], a[1], b0, b1);
            }
        }
    }
#pragma unroll
    for (int mt = 0; mt < 2; mt++){
#pragma unroll
        for (int nt = 0; nt < 8; nt++){
            int i0 = bi*128 + wm*32 + mt*16 + g;
            int jb = bj*128 + wn*64 + nt*8 + ctg*2;
            float b0 = (jb   < N5) ? bias[jb]   : 0.f;
            float b1 = (jb+1 < N5) ? bias[jb+1] : 0.f;
            if (i0 < N5 && jb < N5){
                if (jb+1 < N5)
                    *(float2*)&out[(size_t)i0*N5 + jb] =
                        make_float2(acc[mt][nt][0]+b0, acc[mt][nt][1]+b1);
                else out[(size_t)i0*N5 + jb] = acc[mt][nt][0]+b0;
            }
            if (i0+8 < N5 && jb < N5){
                if (jb+1 < N5)
                    *(float2*)&out[(size_t)(i0+8)*N5 + jb] =
                        make_float2(acc[mt][nt][2]+b0, acc[mt][nt][3]+b1);
                else out[(size_t)(i0+8)*N5 + jb] = acc[mt][nt][2]+b0;
            }
        }
    }
}

__global__ void k_logsoftmax(float* __restrict__ out)
{
    int row = blockIdx.x;
    float* p = out + (size_t)row*N5;
    __shared__ float sh[256];
    float mx = -3.4e38f;
    for (int j = threadIdx.x; j < N5; j += 256) mx = fmaxf(mx, p[j]);
    sh[threadIdx.x] = mx; __syncthreads();
    for (int s = 128; s > 0; s >>= 1){
        if (threadIdx.x < s) sh[threadIdx.x] = fmaxf(sh[threadIdx.x], sh[threadIdx.x+s]);
        __syncthreads();
    }
    mx = sh[0]; __syncthreads();
    float sum = 0.f;
    for (int j = threadIdx.x; j < N5; j += 256) sum += expf(p[j]-mx);
    sh[threadIdx.x] = sum; __syncthreads();
    for (int s = 128; s > 0; s >>= 1){
        if (threadIdx.x < s) sh[threadIdx.x] += sh[threadIdx.x+s];
        __syncthreads();
    }
    float lse = mx + logf(sh[0]);
    for (int j = threadIdx.x; j < N5; j += 256) p[j] -= lse;
}

__global__ void k_copydes(float* __restrict__ out)
{
    int total = N5*256;
    for (int idx = blockIdx.x*blockDim.x + threadIdx.x; idx < total;
         idx += gridDim.x*blockDim.x)
        out[idx] = g_des[idx];
}

// ---------------- launcher ----------------
extern "C" void kernel_launch(void* const* d_in, const int* in_sizes, int n_in,
                              void* d_out, int out_size)
{
    (void)in_sizes; (void)n_in;
    const float* x    = (const float*)d_in[0];
    const float* V    = (const float*)d_in[1];
    const float* A    = (const float*)d_in[2];
    const float* clk  = (const float*)d_in[3];
    const float* Wc[6] = {(const float*)d_in[4], (const float*)d_in[5],
                          (const float*)d_in[6], (const float*)d_in[7],
                          (const float*)d_in[8], (const float*)d_in[9]};
    const float* fc1w = (const float*)d_in[10];
    const float* fc1b = (const float*)d_in[11];
    const float* fc2w = (const float*)d_in[12];
    const float* fc2b = (const float*)d_in[13];
    float* out = (float*)d_out;

    // Build Win (unnormalized M^2) + column norms -> icol2
    k_build_tc<<<dim3(40,40,4),256>>>(V, clk, A);
    k_colreduce<<<dim3(20,4),256>>>();

    // h = fmaxmin(x)
    k_colminmax<<<128,256>>>(x, 128);
    k_apply<<<640,256>>>(x, 128);

    // Layer 1: 128 -> 96
    k_proj<128,96,0><<<dim3(79,5),256>>>(Wc[0], nullptr);
    k_winapply_tc<96><<<dim3(40,8),256>>>();
    k_winreduce<96><<<480,256>>>();
    k_colminmax<<<96,256>>>(nullptr, 96);
    k_apply<<<480,256>>>(nullptr, 96);

    // Layers 2-5: 96 -> 96
    for (int L = 1; L < 5; L++){
        k_proj<96,96,0><<<dim3(79,5),256>>>(Wc[L], nullptr);
        k_winapply_tc<96><<<dim3(40,8),256>>>();
        k_winreduce<96><<<480,256>>>();
        k_colminmax<<<96,256>>>(nullptr, 96);
        k_apply<<<480,256>>>(nullptr, 96);
    }

    // Layer 6: 96 -> 128
    k_proj<96,128,0><<<dim3(79,5),256>>>(Wc[5], nullptr);
    k_winapply_tc<128><<<dim3(40,8),256>>>();
    k_winreduce<128><<<640,256>>>();
    k_colminmax<<<128,256>>>(nullptr, 128);
    k_apply<<<640,256>>>(nullptr, 128);

    // des = elu(h @ fc1_w + fc1_b)
    k_proj<128,256,1><<<dim3(79,1),256>>>(fc1w, fc1b);

    // logits + log_softmax
    k_linear_tc<<<dim3(40,40),256>>>(fc2w, fc2b, out);
    k_logsoftmax<<<5000,256>>>(out);

    // second output: des
    if (out_size >= 25000000 + N5*256)
        k_copydes<<<640,256>>>(out + 25000000);
}

// round 3
// speedup vs baseline: 3.0041x; 1.2567x over previous
#include <cuda_runtime.h>
#include <math.h>

#define N5 5000

// ---------------- scratch (device globals; no allocation allowed) ----------------
__device__ float g_win[100000032];        // [4][5000][5000] (+pad) = M^2, unnormalized
__device__ float g_colpart[4*40*5000];    // per-(z, rowblock) partial column sums
__device__ float g_icol2[4*5000];         // 1 / max(sqrt(sum),eps)^2
__device__ float g_h[5000*128];           // current activations (normalized)
__device__ float g_base[5000*128];        // x@W0 base / post-elu activations
__device__ float g_P[4*5000*128];         // P_k = (h @ W[k+1]) * icol2 (row-scaled)
__device__ float g_part[8*5000*128];      // split-K partials for win-apply
__device__ float g_des[5000*256];
__device__ float g_mn[256];
__device__ float g_mx[256];

__device__ __forceinline__ float eluf(float v){ return v > 0.f ? v : expm1f(v); }

__device__ __forceinline__ unsigned tf32r(float f){
    unsigned u; asm("cvt.rna.tf32.f32 %0, %1;" : "=r"(u) : "f"(f)); return u;
}
__device__ __forceinline__ void splitf(float v, unsigned& hi, unsigned& lo){
    unsigned h = tf32r(v);
    lo = tf32r(v - __uint_as_float(h));
    hi = h;
}
__device__ __forceinline__ void mma8(float* c, const unsigned* a, unsigned b0, unsigned b1){
    asm volatile("mma.sync.aligned.m16n8k8.row.col.f32.tf32.tf32.f32 "
        "{%0,%1,%2,%3},{%4,%5,%6,%7},{%8,%9},{%0,%1,%2,%3};"
        : "+f"(c[0]),"+f"(c[1]),"+f"(c[2]),"+f"(c[3])
        : "r"(a[0]),"r"(a[1]),"r"(a[2]),"r"(a[3]),"r"(b0),"r"(b1));
}

// ---------------- column min/max (axis=0) ----------------
__global__ void k_colminmax(const float* __restrict__ xsrc, int C)
{
    const float* src = xsrc ? xsrc : g_base;
    int c = blockIdx.x;
    float mn = 3.4e38f, mx = -3.4e38f;
    for (int n = threadIdx.x; n < N5; n += blockDim.x){
        float v = src[(size_t)n*C + c];
        mn = fminf(mn, v); mx = fmaxf(mx, v);
    }
    __shared__ float smn[256], smx[256];
    smn[threadIdx.x] = mn; smx[threadIdx.x] = mx; __syncthreads();
    for (int s = 128; s > 0; s >>= 1){
        if (threadIdx.x < s){
            smn[threadIdx.x] = fminf(smn[threadIdx.x], smn[threadIdx.x+s]);
            smx[threadIdx.x] = fmaxf(smx[threadIdx.x], smx[threadIdx.x+s]);
        }
        __syncthreads();
    }
    if (threadIdx.x == 0){ g_mn[c] = smn[0]; g_mx[c] = smx[0]; }
}

__global__ void k_apply(const float* __restrict__ xsrc, int C)
{
    const float* src = xsrc ? xsrc : g_base;
    int total = N5*C;
    for (int idx = blockIdx.x*blockDim.x + threadIdx.x; idx < total;
         idx += gridDim.x*blockDim.x){
        int c = idx % C;
        g_h[idx] = (src[idx] - g_mn[c]) / (g_mx[c] - g_mn[c]);
    }
}

// ---------------- build Win, SYMMETRIC: only bi<=bj tiles; mirror written transposed --------
__global__ __launch_bounds__(256,2) void k_build_sym(const float* __restrict__ V,
                                                     const float* __restrict__ clk,
                                                     const float* __restrict__ A)
{
    __shared__ unsigned smemAB[4][16][136];   // [0]=Ah [1]=Al [2]=Bh [3]=Bl
    __shared__ float scol[4][128];
    __shared__ float msum[2][128];
    unsigned (*Ah)[136] = smemAB[0];
    unsigned (*Al)[136] = smemAB[1];
    unsigned (*Bh)[136] = smemAB[2];
    unsigned (*Bl)[136] = smemAB[3];
    float (*tr)[132] = (float(*)[132])(&smemAB[0][0][0]);  // 32x132 fits in Ah+Al

    const int z = blockIdx.y;
    const int kcol = 31 - 8*z;
    // decode triangular pair index -> (bi, bj), bi <= bj
    int bi = 0, rem = blockIdx.x;
    while (rem >= 40 - bi){ rem -= 40 - bi; bi++; }
    const int bj = bi + rem;

    const int t = threadIdx.x;
    const int w = t >> 5, lane = t & 31, g = lane >> 2, ctg = lane & 3;
    const int wm = w >> 1, wn = w & 1;
    const int r = t >> 1, seg = t & 1;
    const int garow = min(bi*128 + r, N5-1);
    const int gbrow = min(bj*128 + r, N5-1);

    float acc[2][8][4];
#pragma unroll
    for (int mt = 0; mt < 2; mt++)
#pragma unroll
        for (int nt = 0; nt < 8; nt++)
#pragma unroll
            for (int q = 0; q < 4; q++) acc[mt][nt][q] = 0.f;

    for (int c = 0; c < 16; c++){
        const int k0 = c*16;
        __syncthreads();
#pragma unroll
        for (int j = 0; j < 2; j++){
            int col = seg*8 + j*4;
            float4 va = *(const float4*)&V[(size_t)garow*256 + k0 + col];
            va.x *= clk[(k0+col+0)*32 + kcol];
            va.y *= clk[(k0+col+1)*32 + kcol];
            va.z *= clk[(k0+col+2)*32 + kcol];
            va.w *= clk[(k0+col+3)*32 + kcol];
            unsigned h0,l0,h1,l1,h2,l2,h3,l3;
            splitf(va.x,h0,l0); splitf(va.y,h1,l1); splitf(va.z,h2,l2); splitf(va.w,h3,l3);
            Ah[col+0][r]=h0; Al[col+0][r]=l0;
            Ah[col+1][r]=h1; Al[col+1][r]=l1;
            Ah[col+2][r]=h2; Al[col+2][r]=l2;
            Ah[col+3][r]=h3; Al[col+3][r]=l3;

            float4 vb = *(const float4*)&V[(size_t)gbrow*256 + k0 + col];
            splitf(vb.x,h0,l0); splitf(vb.y,h1,l1); splitf(vb.z,h2,l2); splitf(vb.w,h3,l3);
            Bh[col+0][r]=h0; Bl[col+0][r]=l0;
            Bh[col+1][r]=h1; Bl[col+1][r]=l1;
            Bh[col+2][r]=h2; Bl[col+2][r]=l2;
            Bh[col+3][r]=h3; Bl[col+3][r]=l3;
        }
        __syncthreads();
#pragma unroll
        for (int kk = 0; kk < 2; kk++){
            const int k = kk*8;
            unsigned ah[2][4], al[2][4];
#pragma unroll
            for (int mt = 0; mt < 2; mt++){
                int m0 = wm*32 + mt*16;
                ah[mt][0]=Ah[k+ctg][m0+g];   ah[mt][1]=Ah[k+ctg][m0+g+8];
                ah[mt][2]=Ah[k+ctg+4][m0+g]; ah[mt][3]=Ah[k+ctg+4][m0+g+8];
                al[mt][0]=Al[k+ctg][m0+g];   al[mt][1]=Al[k+ctg][m0+g+8];
                al[mt][2]=Al[k+ctg+4][m0+g]; al[mt][3]=Al[k+ctg+4][m0+g+8];
            }
#pragma unroll
            for (int nt = 0; nt < 8; nt++){
                int n = wn*64 + nt*8 + g;
                unsigned bh0 = Bh[k+ctg][n], bh1 = Bh[k+ctg+4][n];
                unsigned bl0 = Bl[k+ctg][n], bl1 = Bl[k+ctg+4][n];
#pragma unroll
                for (int mt = 0; mt < 2; mt++){
                    mma8(acc[mt][nt], ah[mt], bh0, bh1);
                    mma8(acc[mt][nt], ah[mt], bl0, bl1);
                    mma8(acc[mt][nt], al[mt], bh0, bh1);
                }
            }
        }
    }

    const size_t zbase = (size_t)z*25000000;

    // ----- normal tile: X[i][j] = ((T*a_j)^2)^2, colpart[bi][j] -----
#pragma unroll
    for (int nt = 0; nt < 8; nt++){
        int jb = bj*128 + wn*64 + nt*8 + ctg*2;
        float aj0 = (jb   < N5) ? A[jb]   : 0.f;
        float aj1 = (jb+1 < N5) ? A[jb+1] : 0.f;
        float se = 0.f, so = 0.f;
#pragma unroll
        for (int mt = 0; mt < 2; mt++){
            int i0 = bi*128 + wm*32 + mt*16 + g;
            float m00 = acc[mt][nt][0]*aj0; float X00 = m00*m00; X00 *= X00;
            float m01 = acc[mt][nt][1]*aj1; float X01 = m01*m01; X01 *= X01;
            float m10 = acc[mt][nt][2]*aj0; float X10 = m10*m10; X10 *= X10;
            float m11 = acc[mt][nt][3]*aj1; float X11 = m11*m11; X11 *= X11;
            bool ok0 = i0 < N5, ok1 = (i0+8) < N5;
            if (ok0 && jb < N5){
                if (jb+1 < N5) *(float2*)&g_win[zbase + (size_t)i0*N5 + jb] = make_float2(X00,X01);
                else g_win[zbase + (size_t)i0*N5 + jb] = X00;
            }
            if (ok1 && jb < N5){
                if (jb+1 < N5) *(float2*)&g_win[zbase + (size_t)(i0+8)*N5 + jb] = make_float2(X10,X11);
                else g_win[zbase + (size_t)(i0+8)*N5 + jb] = X10;
            }
            se += (ok0?X00:0.f) + (ok1?X10:0.f);
            so += (ok0?X01:0.f) + (ok1?X11:0.f);
        }
#pragma unroll
        for (int off = 4; off < 32; off <<= 1){
            se += __shfl_xor_sync(0xffffffffu, se, off);
            so += __shfl_xor_sync(0xffffffffu, so, off);
        }
        if (lane < 4){
            scol[wm][wn*64 + nt*8 + lane*2]     = se;
            scol[wm][wn*64 + nt*8 + lane*2 + 1] = so;
        }
    }
    __syncthreads();
    if (t < 128){
        float s = scol[0][t] + scol[1][t] + scol[2][t] + scol[3][t];
        int j = bj*128 + t;
        if (j < N5) g_colpart[((size_t)z*40 + bi)*N5 + j] = s;
    }

    if (bi == bj) return;

    // ----- mirror tile: Xm[j][i] = ((T*a_i)^2)^2, colpart[bj][i] -----
    float ai[2][2];
#pragma unroll
    for (int mt = 0; mt < 2; mt++){
        int i0 = bi*128 + wm*32 + mt*16 + g;   // bi<=38 -> always < N5
        ai[mt][0] = A[i0];
        ai[mt][1] = A[i0+8];
    }

    // row sums over this block's j range, per i
    float rs[2][2] = {{0.f,0.f},{0.f,0.f}};
#pragma unroll
    for (int nt = 0; nt < 8; nt++){
        int jb = bj*128 + wn*64 + nt*8 + ctg*2;
        bool j0ok = jb < N5, j1ok = (jb+1) < N5;
#pragma unroll
        for (int mt = 0; mt < 2; mt++){
            float m00 = acc[mt][nt][0]*ai[mt][0]; float X00 = m00*m00; X00 *= X00;
            float m01 = acc[mt][nt][1]*ai[mt][0]; float X01 = m01*m01; X01 *= X01;
            float m10 = acc[mt][nt][2]*ai[mt][1]; float X10 = m10*m10; X10 *= X10;
            float m11 = acc[mt][nt][3]*ai[mt][1]; float X11 = m11*m11; X11 *= X11;
            rs[mt][0] += (j0ok?X00:0.f) + (j1ok?X01:0.f);
            rs[mt][1] += (j0ok?X10:0.f) + (j1ok?X11:0.f);
        }
    }
#pragma unroll
    for (int off = 1; off < 4; off <<= 1){
#pragma unroll
        for (int mt = 0; mt < 2; mt++){
            rs[mt][0] += __shfl_xor_sync(0xffffffffu, rs[mt][0], off);
            rs[mt][1] += __shfl_xor_sync(0xffffffffu, rs[mt][1], off);
        }
    }
    if (ctg == 0){
#pragma unroll
        for (int mt = 0; mt < 2; mt++){
            if (wn == 0){
                msum[0][wm*32 + mt*16 + g]     = rs[mt][0];
                msum[0][wm*32 + mt*16 + g + 8] = rs[mt][1];
            } else {
                msum[1][wm*32 + mt*16 + g]     = rs[mt][0];
                msum[1][wm*32 + mt*16 + g + 8] = rs[mt][1];
            }
        }
    }
    __syncthreads();
    if (t < 128)
        g_colpart[((size_t)z*40 + bj)*N5 + bi*128 + t] = msum[0][t] + msum[1][t];

    // staged transpose write of mirror tile, 4 chunks of 32 j-rows
    for (int c = 0; c < 4; c++){
        __syncthreads();
        if (wn == (c >> 1)){
#pragma unroll
            for (int q = 0; q < 4; q++){
                int nt = (c & 1)*4 + q;
                int jl = nt*8 + ctg*2 - (c & 1)*32;      // 0..30
#pragma unroll
                for (int mt = 0; mt < 2; mt++){
                    int il = wm*32 + mt*16 + g;
                    float m00 = acc[mt][nt][0]*ai[mt][0]; float X00 = m00*m00; X00 *= X00;
                    float m01 = acc[mt][nt][1]*ai[mt][0]; float X01 = m01*m01; X01 *= X01;
                    float m10 = acc[mt][nt][2]*ai[mt][1]; float X10 = m10*m10; X10 *= X10;
                    float m11 = acc[mt][nt][3]*ai[mt][1]; float X11 = m11*m11; X11 *= X11;
                    tr[jl  ][il]   = X00;
                    tr[jl  ][il+8] = X10;
                    tr[jl+1][il]   = X01;
                    tr[jl+1][il+8] = X11;
                }
            }
        }
        __syncthreads();
        int jg0 = bj*128 + c*32;
        for (int idx = t; idx < 32*32; idx += 256){
            int row = idx >> 5, c4 = (idx & 31)*4;
            int jg = jg0 + row;
            if (jg < N5)
                *(float4*)&g_win[zbase + (size_t)jg*N5 + bi*128 + c4] =
                    *(float4*)&tr[row][c4];
        }
    }
}

__global__ void k_colreduce()
{
    int z = blockIdx.y;
    int j = blockIdx.x*blockDim.x + threadIdx.x;
    if (j < N5){
        float s = 0.f;
        for (int b = 0; b < 40; b++) s += g_colpart[((size_t)z*40 + b)*N5 + j];
        float c = fmaxf(sqrtf(s), 1e-12f);
        g_icol2[z*N5 + j] = 1.0f/(c*c);
    }
}

// ---------------- tensor-core proj: base = h@W[0], P_k = (h@W[k+1])*icol2 ----------------
// h split hi/lo (2 MMA), W plain tf32.
template<int CI, int CO>
__global__ __launch_bounds__(256,2) void k_proj_tc(const float* __restrict__ W)
{
    constexpr int NT = CO/16;
    __shared__ unsigned Hh[128][17], Hl[128][17];
    __shared__ unsigned Ws[16][CO+4];

    const int j = blockIdx.y;
    const float* Wj = W + (size_t)j*CI*CO;
    const int r0 = blockIdx.x*128;
    const int t = threadIdx.x;
    const int w = t >> 5, lane = t & 31, g = lane >> 2, ctg = lane & 3;
    const int wm = w >> 1, wn = w & 1;

    float acc[2][NT][4];
#pragma unroll
    for (int mt = 0; mt < 2; mt++)
#pragma unroll
        for (int nt = 0; nt < NT; nt++)
#pragma unroll
            for (int q = 0; q < 4; q++) acc[mt][nt][q] = 0.f;

    for (int c0 = 0; c0 < CI; c0 += 16){
        __syncthreads();
#pragma unroll
        for (int i = 0; i < 2; i++){
            int idx = t + i*256;               // 0..511
            int m = idx >> 2, k4 = (idx & 3)*4;
            int gr = min(r0 + m, N5-1);
            float4 v = *(const float4*)&g_h[(size_t)gr*CI + c0 + k4];
            unsigned h0,l0;
            splitf(v.x,h0,l0); Hh[m][k4+0]=h0; Hl[m][k4+0]=l0;
            splitf(v.y,h0,l0); Hh[m][k4+1]=h0; Hl[m][k4+1]=l0;
            splitf(v.z,h0,l0); Hh[m][k4+2]=h0; Hl[m][k4+2]=l0;
            splitf(v.w,h0,l0); Hh[m][k4+3]=h0; Hl[m][k4+3]=l0;
        }
        for (int idx = t; idx < 16*CO; idx += 256){
            int kk2 = idx / CO, o = idx % CO;
            Ws[kk2][o] = tf32r(Wj[(size_t)(c0+kk2)*CO + o]);
        }
        __syncthreads();
#pragma unroll
        for (int kk = 0; kk < 2; kk++){
            const int k = kk*8;
            unsigned ah[2][4], al[2][4];
#pragma unroll
            for (int mt = 0; mt < 2; mt++){
                int m0 = wm*32 + mt*16;
                ah[mt][0]=Hh[m0+g][k+ctg];   ah[mt][1]=Hh[m0+g+8][k+ctg];
                ah[mt][2]=Hh[m0+g][k+ctg+4]; ah[mt][3]=Hh[m0+g+8][k+ctg+4];
                al[mt][0]=Hl[m0+g][k+ctg];   al[mt][1]=Hl[m0+g+8][k+ctg];
                al[mt][2]=Hl[m0+g][k+ctg+4]; al[mt][3]=Hl[m0+g+8][k+ctg+4];
            }
#pragma unroll
            for (int nt = 0; nt < NT; nt++){
                int n = wn*(CO/2) + nt*8 + g;
                unsigned b0 = Ws[k+ctg][n], b1 = Ws[k+ctg+4][n];
#pragma unroll
                for (int mt = 0; mt < 2; mt++){
                    mma8(acc[mt][nt], ah[mt], b0, b1);
                    mma8(acc[mt][nt], al[mt], b0, b1);
                }
            }
        }
    }

    float* out = (j == 0) ? g_base : g_P + (size_t)(j-1)*N5*CO;
#pragma unroll
    for (int mt = 0; mt < 2; mt++){
        int i0 = r0 + wm*32 + mt*16 + g;
        float s0 = 1.f, s8 = 1.f;
        if (j > 0){
            s0 = (i0   < N5) ? g_icol2[(j-1)*N5 + i0]   : 0.f;
            s8 = (i0+8 < N5) ? g_icol2[(j-1)*N5 + i0+8] : 0.f;
        }
#pragma unroll
        for (int nt = 0; nt < NT; nt++){
            int n = wn*(CO/2) + nt*8 + ctg*2;
            if (i0 < N5)
                *(float2*)&out[(size_t)i0*CO + n] =
                    make_float2(acc[mt][nt][0]*s0, acc[mt][nt][1]*s0);
            if (i0+8 < N5)
                *(float2*)&out[(size_t)(i0+8)*CO + n] =
                    make_float2(acc[mt][nt][2]*s8, acc[mt][nt][3]*s8);
        }
    }
}

// ---------------- SIMT proj for des (bias + elu) ----------------
template<int CI, int CO>
__global__ __launch_bounds__(256) void k_proj_des(const float* __restrict__ W,
                                                  const float* __restrict__ bias)
{
    constexpr int PER = (64*CO)/256;
    const float* Wj = W;
    const int r0 = blockIdx.x*64;
    const int t = threadIdx.x;

    __shared__ float ht[64][33];
    __shared__ float Wt[32][CO+1];

    float acc[PER];
#pragma unroll
    for (int p = 0; p < PER; p++) acc[p] = 0.f;

    for (int c0 = 0; c0 < CI; c0 += 32){
        for (int idx = t; idx < 64*32; idx += 256){
            int r = idx >> 5, cc = idx & 31;
            int gr = r0 + r;
            ht[r][cc] = (gr < N5) ? g_h[(size_t)gr*CI + c0 + cc] : 0.f;
        }
        for (int idx = t; idx < 32*CO; idx += 256){
            int cc = idx / CO, o = idx % CO;
            Wt[cc][o] = Wj[(size_t)(c0+cc)*CO + o];
        }
        __syncthreads();
#pragma unroll
        for (int p = 0; p < PER; p++){
            int oi = t + p*256;
            int rr = oi / CO, o = oi % CO;
            float s = acc[p];
#pragma unroll
            for (int cc = 0; cc < 32; cc++) s += ht[rr][cc]*Wt[cc][o];
            acc[p] = s;
        }
        __syncthreads();
    }
#pragma unroll
    for (int p = 0; p < PER; p++){
        int oi = t + p*256;
        int rr = oi / CO, o = oi % CO;
        int gr = r0 + rr;
        if (gr < N5)
            g_des[(size_t)gr*CO + o] = eluf(acc[p] + bias[o]);
    }
}

// ---------------- big fused GEMM (tensor core): part_y = Win_chunk @ Pscaled ----------------
template<int BN>
__global__ __launch_bounds__(256,2) void k_winapply_tc()
{
    constexpr int BP = (BN==96) ? 104 : 136;
    constexpr int NT = BN/16;
    constexpr int NB4 = BN/4;
    constexpr int BCNT = (32*NB4)/256;
    __shared__ unsigned As[32][136];
    __shared__ __align__(16) unsigned Bs[32][BP];

    const int t = threadIdx.x;
    const int w = t >> 5, lane = t & 31, g = lane >> 2, ctg = lane & 3;
    const int wm = w >> 1, wn = w & 1;
    const int bi = blockIdx.x, y = blockIdx.y;
    const int slab = y >> 1;
    const int kbase = (y & 1) ? 2496 : 0;
    const int nch   = (y & 1) ? 79 : 78;
    const float* __restrict__ Wk = g_win + (size_t)slab*25000000;
    const float* __restrict__ Pk = g_P + (size_t)slab*N5*BN;
    const int ar = t >> 1, aseg = t & 1;
    const float* aptr = Wk + (size_t)min(bi*128 + ar, N5-1)*N5;

    float4 aR[4], bR[BCNT];

    {
        const int k0 = kbase + aseg*16;
#pragma unroll
        for (int j = 0; j < 4; j++) aR[j] = *(const float4*)&aptr[k0 + j*4];
#pragma unroll
        for (int i = 0; i < BCNT; i++){
            int idx = t + i*256;
            int br = idx/NB4, bc = idx%NB4;
            int gk = kbase + br;
            bR[i] = (gk < N5) ? *(const float4*)&Pk[(size_t)gk*BN + bc*4]
                              : make_float4(0,0,0,0);
        }
    }

    float acc[2][NT][4];
#pragma unroll
    for (int mt = 0; mt < 2; mt++)
#pragma unroll
        for (int nt = 0; nt < NT; nt++)
#pragma unroll
            for (int q = 0; q < 4; q++) acc[mt][nt][q] = 0.f;

    for (int c = 0; c < nch; c++){
        __syncthreads();
#pragma unroll
        for (int j = 0; j < 4; j++){
            int col = aseg*16 + j*4;
            As[col+0][ar] = tf32r(aR[j].x);
            As[col+1][ar] = tf32r(aR[j].y);
            As[col+2][ar] = tf32r(aR[j].z);
            As[col+3][ar] = tf32r(aR[j].w);
        }
#pragma unroll
        for (int i = 0; i < BCNT; i++){
            int idx = t + i*256;
            int br = idx/NB4, bc = idx%NB4;
            *(uint4*)&Bs[br][bc*4] = make_uint4(tf32r(bR[i].x), tf32r(bR[i].y),
                                                tf32r(bR[i].z), tf32r(bR[i].w));
        }
        __syncthreads();
        if (c+1 < nch){
            const int k0 = kbase + (c+1)*32;
#pragma unroll
            for (int j = 0; j < 4; j++) aR[j] = *(const float4*)&aptr[k0 + aseg*16 + j*4];
#pragma unroll
            for (int i = 0; i < BCNT; i++){
                int idx = t + i*256;
                int br = idx/NB4, bc = idx%NB4;
                int gk = k0 + br;
                bR[i] = (gk < N5) ? *(const float4*)&Pk[(size_t)gk*BN + bc*4]
                                  : make_float4(0,0,0,0);
            }
        }
#pragma unroll
        for (int kk = 0; kk < 4; kk++){
            const int k = kk*8;
            unsigned a[2][4];
#pragma unroll
            for (int mt = 0; mt < 2; mt++){
                int m0 = wm*32 + mt*16;
                a[mt][0]=As[k+ctg][m0+g];   a[mt][1]=As[k+ctg][m0+g+8];
                a[mt][2]=As[k+ctg+4][m0+g]; a[mt][3]=As[k+ctg+4][m0+g+8];
            }
#pragma unroll
            for (int nt = 0; nt < NT; nt++){
                int n = wn*(BN/2) + nt*8 + g;
                unsigned b0 = Bs[k+ctg][n], b1 = Bs[k+ctg+4][n];
                mma8(acc[0][nt], a[0], b0, b1);
                mma8(acc[1][nt], a[1], b0, b1);
            }
        }
    }

    float* dst = g_part + (size_t)y*N5*BN;
#pragma unroll
    for (int mt = 0; mt < 2; mt++){
#pragma unroll
        for (int nt = 0; nt < NT; nt++){
            int i0 = bi*128 + wm*32 + mt*16 + g;
            int n  = wn*(BN/2) + nt*8 + ctg*2;
            if (i0 < N5)
                *(float2*)&dst[(size_t)i0*BN + n] =
                    make_float2(acc[mt][nt][0], acc[mt][nt][1]);
            if (i0+8 < N5)
                *(float2*)&dst[(size_t)(i0+8)*BN + n] =
                    make_float2(acc[mt][nt][2], acc[mt][nt][3]);
        }
    }
}

template<int BN>
__global__ void k_winreduce()
{
    int total = N5*BN;
    for (int idx = blockIdx.x*blockDim.x + threadIdx.x; idx < total;
         idx += gridDim.x*blockDim.x){
        float v = g_base[idx];
#pragma unroll
        for (int s = 0; s < 8; s++) v += g_part[(size_t)s*N5*BN + idx];
        g_base[idx] = eluf(v);
    }
}

// ---------------- logits = des @ fc2_w + fc2_b (tensor core, plain tf32) ----------------
__global__ __launch_bounds__(256,2) void k_linear_tc(const float* __restrict__ B,
                                                     const float* __restrict__ bias,
                                                     float* __restrict__ out)
{
    __shared__ unsigned As[32][136];
    __shared__ __align__(16) unsigned Bs[32][136];

    const int t = threadIdx.x;
    const int w = t >> 5, lane = t & 31, g = lane >> 2, ctg = lane & 3;
    const int wm = w >> 1, wn = w & 1;
    const int bi = blockIdx.y, bj = blockIdx.x;
    const int ar = t >> 1, aseg = t & 1;
    const float* aptr = g_des + (size_t)min(bi*128 + ar, N5-1)*256;

    float acc[2][8][4];
#pragma unroll
    for (int mt = 0; mt < 2; mt++)
#pragma unroll
        for (int nt = 0; nt < 8; nt++)
#pragma unroll
            for (int q = 0; q < 4; q++) acc[mt][nt][q] = 0.f;

    for (int c = 0; c < 8; c++){
        const int k0 = c*32;
        __syncthreads();
#pragma unroll
        for (int j = 0; j < 4; j++){
            int col = aseg*16 + j*4;
            float4 v = *(const float4*)&aptr[k0 + col];
            As[col+0][ar] = tf32r(v.x);
            As[col+1][ar] = tf32r(v.y);
            As[col+2][ar] = tf32r(v.z);
            As[col+3][ar] = tf32r(v.w);
        }
#pragma unroll
        for (int i = 0; i < 4; i++){
            int idx = t + i*256;
            int br = idx >> 5, bc = idx & 31;
            int gj = bj*128 + bc*4;
            float4 v;
            if (gj + 3 < N5) v = *(const float4*)&B[(size_t)(k0+br)*N5 + gj];
            else {
                v = make_float4(0,0,0,0);
                if (gj+0 < N5) v.x = B[(size_t)(k0+br)*N5 + gj+0];
                if (gj+1 < N5) v.y = B[(size_t)(k0+br)*N5 + gj+1];
                if (gj+2 < N5) v.z = B[(size_t)(k0+br)*N5 + gj+2];
                if (gj+3 < N5) v.w = B[(size_t)(k0+br)*N5 + gj+3];
            }
            *(uint4*)&Bs[br][bc*4] = make_uint4(tf32r(v.x), tf32r(v.y), tf32r(v.z), tf32r(v.w));
        }
        __syncthreads();
#pragma unroll
        for (int kk = 0; kk < 4; kk++){
            const int k = kk*8;
            unsigned a[2][4];
#pragma unroll
            for (int mt = 0; mt < 2; mt++){
                int m0 = wm*32 + mt*16;
                a[mt][0]=As[k+ctg][m0+g];   a[mt][1]=As[k+ctg][m0+g+8];
                a[mt][2]=As[k+ctg+4][m0+g]; a[mt][3]=As[k+ctg+4][m0+g+8];
            }
#pragma unroll
            for (int nt = 0; nt < 8; nt++){
                int n = wn*64 + nt*8 + g;
                unsigned b0 = Bs[k+ctg][n], b1 = Bs[k+ctg+4][n];
                mma8(acc[0][nt], a[0], b0, b1);
                mma8(acc[1][nt], a[1], b0, b1);
            }
        }
    }
#pragma unroll
    for (int mt = 0; mt < 2; mt++){
#pragma unroll
        for (int nt = 0; nt < 8; nt++){
            int i0 = bi*128 + wm*32 + mt*16 + g;
            int jb = bj*128 + wn*64 + nt*8 + ctg*2;
            float b0 = (jb   < N5) ? bias[jb]   : 0.f;
            float b1 = (jb+1 < N5) ? bias[jb+1] : 0.f;
            if (i0 < N5 && jb < N5){
                if (jb+1 < N5)
                    *(float2*)&out[(size_t)i0*N5 + jb] =
                        make_float2(acc[mt][nt][0]+b0, acc[mt][nt][1]+b1);
                else out[(size_t)i0*N5 + jb] = acc[mt][nt][0]+b0;
            }
            if (i0+8 < N5 && jb < N5){
                if (jb+1 < N5)
                    *(float2*)&out[(size_t)(i0+8)*N5 + jb] =
                        make_float2(acc[mt][nt][2]+b0, acc[mt][nt][3]+b1);
                else out[(size_t)(i0+8)*N5 + jb] = acc[mt][nt][2]+b0;
            }
        }
    }
}

// ---------------- log-softmax, register-resident (1R + 1W) ----------------
__global__ void k_logsoftmax(float* __restrict__ out)
{
    const int row = blockIdx.x;
    float* p = out + (size_t)row*N5;
    const int t = threadIdx.x;
    float4 v[5];
    bool have[5];
    float mx = -3.4e38f;
#pragma unroll
    for (int s = 0; s < 5; s++){
        int i4 = t + s*256;
        have[s] = i4 < 1250;                    // 5000/4 exactly
        if (have[s]){
            v[s] = *(const float4*)&p[i4*4];
            mx = fmaxf(mx, fmaxf(fmaxf(v[s].x, v[s].y), fmaxf(v[s].z, v[s].w)));
        }
    }
    __shared__ float sh[256];
    sh[t] = mx; __syncthreads();
    for (int s = 128; s > 0; s >>= 1){
        if (t < s) sh[t] = fmaxf(sh[t], sh[t+s]);
        __syncthreads();
    }
    mx = sh[0]; __syncthreads();
    float sum = 0.f;
#pragma unroll
    for (int s = 0; s < 5; s++)
        if (have[s])
            sum += expf(v[s].x-mx) + expf(v[s].y-mx) + expf(v[s].z-mx) + expf(v[s].w-mx);
    sh[t] = sum; __syncthreads();
    for (int s = 128; s > 0; s >>= 1){
        if (t < s) sh[t] += sh[t+s];
        __syncthreads();
    }
    float lse = mx + logf(sh[0]);
#pragma unroll
    for (int s = 0; s < 5; s++){
        if (have[s]){
            int i4 = t + s*256;
            *(float4*)&p[i4*4] = make_float4(v[s].x-lse, v[s].y-lse, v[s].z-lse, v[s].w-lse);
        }
    }
}

__global__ void k_copydes(float* __restrict__ out)
{
    int total = N5*256;
    for (int idx = blockIdx.x*blockDim.x + threadIdx.x; idx < total;
         idx += gridDim.x*blockDim.x)
        out[idx] = g_des[idx];
}

// ---------------- launcher ----------------
extern "C" void kernel_launch(void* const* d_in, const int* in_sizes, int n_in,
                              void* d_out, int out_size)
{
    (void)in_sizes; (void)n_in;
    const float* x    = (const float*)d_in[0];
    const float* V    = (const float*)d_in[1];
    const float* A    = (const float*)d_in[2];
    const float* clk  = (const float*)d_in[3];
    const float* Wc[6] = {(const float*)d_in[4], (const float*)d_in[5],
                          (const float*)d_in[6], (const float*)d_in[7],
                          (const float*)d_in[8], (const float*)d_in[9]};
    const float* fc1w = (const float*)d_in[10];
    const float* fc1b = (const float*)d_in[11];
    const float* fc2w = (const float*)d_in[12];
    const float* fc2b = (const float*)d_in[13];
    float* out = (float*)d_out;

    // Build Win (unnormalized M^2, symmetric tiles) + column norms -> icol2
    k_build_sym<<<dim3(820,4),256>>>(V, clk, A);
    k_colreduce<<<dim3(20,4),256>>>();

    // h = fmaxmin(x)
    k_colminmax<<<128,256>>>(x, 128);
    k_apply<<<640,256>>>(x, 128);

    // Layer 1: 128 -> 96
    k_proj_tc<128,96><<<dim3(40,5),256>>>(Wc[0]);
    k_winapply_tc<96><<<dim3(40,8),256>>>();
    k_winreduce<96><<<480,256>>>();
    k_colminmax<<<96,256>>>(nullptr, 96);
    k_apply<<<480,256>>>(nullptr, 96);

    // Layers 2-5: 96 -> 96
    for (int L = 1; L < 5; L++){
        k_proj_tc<96,96><<<dim3(40,5),256>>>(Wc[L]);
        k_winapply_tc<96><<<dim3(40,8),256>>>();
        k_winreduce<96><<<480,256>>>();
        k_colminmax<<<96,256>>>(nullptr, 96);
        k_apply<<<480,256>>>(nullptr, 96);
    }

    // Layer 6: 96 -> 128
    k_proj_tc<96,128><<<dim3(40,5),256>>>(Wc[5]);
    k_winapply_tc<128><<<dim3(40,8),256>>>();
    k_winreduce<128><<<640,256>>>();
    k_colminmax<<<128,256>>>(nullptr, 128);
    k_apply<<<640,256>>>(nullptr, 128);

    // des = elu(h @ fc1_w + fc1_b)
    k_proj_des<128,256><<<79,256>>>(fc1w, fc1b);

    // logits + log_softmax
    k_linear_tc<<<dim3(40,40),256>>>(fc2w, fc2b, out);
    k_logsoftmax<<<5000,256>>>(out);

    // second output: des
    if (out_size >= 25000000 + N5*256)
        k_copydes<<<640,256>>>(out + 25000000);
}